// round 14
// baseline (speedup 1.0000x reference)
#include <cuda_runtime.h>
#include <cuda_bf16.h>
#include <cstdint>
#include <cstddef>

// ---------------------------------------------------------------------------
// InternVL2.5 Attention: B=8, N=1025, C=3200, H=25, D=128
// Round 13: dense GEMM pipeline deepened to 3 stages (prefetch distance 2)
// + B-side ldmatrix.x4. Numerics identical to round 12 (3-product bf16).
// Flash middle (no-softmax-chain variant) unchanged.
// ---------------------------------------------------------------------------

namespace {
constexpr int kB = 8, kN = 1025, kC = 3200, kH = 25, kD = 128;
constexpr int kM = kB * kN;          // 8200
constexpr int kQKVN = 3 * kC;        // 9600
constexpr int kKP = 1088;            // padded key count (17*64)
constexpr float kScale = 0.08838834764831845f;
constexpr float kEps = 1e-6f;

// mma.sync dense GEMM config
constexpr int GBM = 128, GBN = 128, GBK = 64;
constexpr int TILE_B = GBM * GBK * 2;          // 16 KB per tensor tile
constexpr int STAGE_B = 4 * TILE_B;            // 64 KB
constexpr int GS = 3;                          // pipeline stages
constexpr int TC_SMEM = GS * STAGE_B;          // 192 KB

// flash kernel smem: q 64KB + 2 stages x 64KB (k 32KB + v 32KB)
constexpr int FL_SMEM = 3 * 65536;             // 192 KB
}  // namespace

// ---------------- scratch (__device__ globals; no allocation allowed) -------
__device__ float g_qkv[(size_t)8200 * 9600];                // 315 MB
__device__ __nv_bfloat16 g_xh[26240000], g_xl[26240000];
__device__ __nv_bfloat16 g_w1h[30720000], g_w1l[30720000];  // qkv_w^T
__device__ __nv_bfloat16 g_w2h[10240000], g_w2l[10240000];  // proj_w^T
__device__ __nv_bfloat16 g_aoh[26240000], g_aol[26240000];  // O splits
__device__ __nv_bfloat16 g_qh[26240000], g_ql[26240000];    // q split
__device__ __nv_bfloat16 g_kh[26240000], g_kl[26240000];    // k split
__device__ __nv_bfloat16 g_vth[(size_t)200 * 128 * kKP];    // V^T split
__device__ __nv_bfloat16 g_vtl[(size_t)200 * 128 * kKP];

// ---------------- PTX helpers ----------------------------------------------
__device__ __forceinline__ uint32_t smem_u32(const void* p) {
    uint32_t a;
    asm("{ .reg .u64 t; cvta.to.shared.u64 t, %1; cvt.u32.u64 %0, t; }"
        : "=r"(a) : "l"(p));
    return a;
}
__device__ __forceinline__ void ldsm_x4(uint32_t (&r)[4], uint32_t addr) {
    asm volatile("ldmatrix.sync.aligned.m8n8.x4.shared.b16 {%0,%1,%2,%3}, [%4];"
                 : "=r"(r[0]), "=r"(r[1]), "=r"(r[2]), "=r"(r[3]) : "r"(addr));
}
__device__ __forceinline__ void ldsm_x2(uint32_t (&r)[2], uint32_t addr) {
    asm volatile("ldmatrix.sync.aligned.m8n8.x2.shared.b16 {%0,%1}, [%2];"
                 : "=r"(r[0]), "=r"(r[1]) : "r"(addr));
}
__device__ __forceinline__ void mma_bf16(float (&d)[4], const uint32_t (&a)[4],
                                         const uint32_t (&b)[2]) {
    asm volatile(
        "mma.sync.aligned.m16n8k16.row.col.f32.bf16.bf16.f32 "
        "{%0,%1,%2,%3}, {%4,%5,%6,%7}, {%8,%9}, {%0,%1,%2,%3};"
        : "+f"(d[0]), "+f"(d[1]), "+f"(d[2]), "+f"(d[3])
        : "r"(a[0]), "r"(a[1]), "r"(a[2]), "r"(a[3]), "r"(b[0]), "r"(b[1]));
}
__device__ __forceinline__ void mma_bf16s(float (&d)[4], const uint32_t (&a)[4],
                                          uint32_t b0, uint32_t b1) {
    asm volatile(
        "mma.sync.aligned.m16n8k16.row.col.f32.bf16.bf16.f32 "
        "{%0,%1,%2,%3}, {%4,%5,%6,%7}, {%8,%9}, {%0,%1,%2,%3};"
        : "+f"(d[0]), "+f"(d[1]), "+f"(d[2]), "+f"(d[3])
        : "r"(a[0]), "r"(a[1]), "r"(a[2]), "r"(a[3]), "r"(b0), "r"(b1));
}
__device__ __forceinline__ uint32_t swz(uint32_t off) {
    return off ^ ((off >> 3) & 0x70);
}
__device__ __forceinline__ uint32_t packbf(float lo, float hi) {
    __nv_bfloat162 h;
    h.x = __float2bfloat16(lo);
    h.y = __float2bfloat16(hi);
    return *reinterpret_cast<uint32_t*>(&h);
}
__device__ __forceinline__ float bfres(float v) {
    return v - __bfloat162float(__float2bfloat16(v));
}

// ---------------------------------------------------------------------------
// HMMA dense GEMM core, 3-stage pipeline:
// C[M,N] = Ahl[M,K]*(Bhl[N,K])^T + bias
// ---------------------------------------------------------------------------
__device__ __forceinline__ void gemm_core(
    const __nv_bfloat16* __restrict__ Ah, const __nv_bfloat16* __restrict__ Al,
    const __nv_bfloat16* __restrict__ Bh, const __nv_bfloat16* __restrict__ Bl,
    const float* __restrict__ bias, float* __restrict__ C,
    int M, int N, int K, int lda, int ldb, int ldc,
    int rowBase, int colBase, uint32_t sm0) {
    const int tid = threadIdx.x;
    const int lane = tid & 31;
    const int warp = tid >> 5;
    const int m0 = (warp >> 2) * 64;
    const int n0 = (warp & 3) * 32;
    const int nChunks = K / GBK;

    float acc[4][4][4] = {};

    auto load_stage = [&](int c) {
        const uint32_t sb = sm0 + (uint32_t)(c % GS) * STAGE_B;
        const int k0 = c * GBK;
#pragma unroll
        for (int t = 0; t < 16; t++) {
            int cid = tid + (t << 8);
            int tensor = cid >> 10;
            int r = (cid >> 3) & 127;
            int ck = cid & 7;
            bool isA = tensor < 2;
            int g0 = (isA ? rowBase : colBase) + r;
            int lim = isA ? M : N;
            int sz = (g0 < lim) ? 16 : 0;
            int ga = (g0 < lim) ? g0 : 0;
            int ld = isA ? lda : ldb;
            const __nv_bfloat16* bp = (tensor == 0) ? Ah : (tensor == 1) ? Al
                                      : (tensor == 2) ? Bh : Bl;
            const void* gp = bp + (size_t)ga * ld + k0 + (ck << 3);
            uint32_t off = (uint32_t)((r << 7) + (ck << 4));
            uint32_t d = sb + tensor * TILE_B + swz(off);
            asm volatile("cp.async.cg.shared.global [%0], [%1], 16, %2;"
                         :: "r"(d), "l"(gp), "r"(sz));
        }
        asm volatile("cp.async.commit_group;" ::: "memory");
    };

    auto compute_stage = [&](int s) {
        const uint32_t sb = sm0 + (uint32_t)s * STAGE_B;
        const uint32_t aRowA = (uint32_t)(m0 + (lane & 15));
        const uint32_t aByteHalf = (uint32_t)((lane >> 4) << 4);
        // B x4 addressing: lanes 0-15 -> rows nfp*16+(lane&7) (k-halves),
        // lanes 16-31 -> rows +8. Fragments: [0,1]=nf even, [2,3]=nf odd.
        const uint32_t bRow = (uint32_t)(n0 + (lane & 7) + ((lane >> 4) << 3));
        const uint32_t bByteHalf = (uint32_t)(((lane >> 3) & 1) << 4);
#pragma unroll
        for (int ks = 0; ks < 4; ks++) {
            const uint32_t kb = (uint32_t)(ks << 5);
            uint32_t bh4[2][4], bl4[2][4];
#pragma unroll
            for (int nfp = 0; nfp < 2; nfp++) {
                uint32_t off = (((bRow + (uint32_t)(nfp * 16)) << 7) + kb + bByteHalf);
                uint32_t sa = swz(off);
                ldsm_x4(bh4[nfp], sb + 2 * TILE_B + sa);
                ldsm_x4(bl4[nfp], sb + 3 * TILE_B + sa);
            }
#pragma unroll
            for (int mf = 0; mf < 4; mf++) {
                uint32_t off = (((aRowA + mf * 16) << 7) + kb + aByteHalf);
                uint32_t sa = swz(off);
                uint32_t a[4];
                ldsm_x4(a, sb + sa);                 // Ah
#pragma unroll
                for (int nf = 0; nf < 4; nf++) {
                    mma_bf16s(acc[mf][nf], a, bh4[nf >> 1][(nf & 1) * 2],
                              bh4[nf >> 1][(nf & 1) * 2 + 1]);
                    mma_bf16s(acc[mf][nf], a, bl4[nf >> 1][(nf & 1) * 2],
                              bl4[nf >> 1][(nf & 1) * 2 + 1]);
                }
                ldsm_x4(a, sb + TILE_B + sa);        // Al
#pragma unroll
                for (int nf = 0; nf < 4; nf++)
                    mma_bf16s(acc[mf][nf], a, bh4[nf >> 1][(nf & 1) * 2],
                              bh4[nf >> 1][(nf & 1) * 2 + 1]);
            }
        }
    };

    // 3-stage: prefetch distance 2.
    load_stage(0);
    if (nChunks > 1) load_stage(1);
    for (int c = 0; c < nChunks; c++) {
        if (c == nChunks - 1) {
            asm volatile("cp.async.wait_group 0;" ::: "memory");
        } else {
            asm volatile("cp.async.wait_group 1;" ::: "memory");
        }
        __syncthreads();
        if (c + 2 < nChunks) load_stage(c + 2);
        compute_stage(c % GS);
        __syncthreads();
    }

#pragma unroll
    for (int mf = 0; mf < 4; mf++) {
        int r0 = rowBase + m0 + mf * 16 + (lane >> 2);
#pragma unroll
        for (int nf = 0; nf < 4; nf++) {
            int col = colBase + n0 + nf * 8 + ((lane & 3) << 1);
            float bx = 0.f, by = 0.f;
            if (bias && col + 1 < N) { float2 bv = *(const float2*)&bias[col]; bx = bv.x; by = bv.y; }
            if (r0 < M) {
                if (col + 1 < N) {
                    float2 o = {acc[mf][nf][0] + bx, acc[mf][nf][1] + by};
                    *(float2*)&C[(size_t)r0 * ldc + col] = o;
                } else if (col < N) {
                    C[(size_t)r0 * ldc + col] = acc[mf][nf][0] + bx;
                }
            }
            if (r0 + 8 < M) {
                if (col + 1 < N) {
                    float2 o = {acc[mf][nf][2] + bx, acc[mf][nf][3] + by};
                    *(float2*)&C[(size_t)(r0 + 8) * ldc + col] = o;
                } else if (col < N) {
                    C[(size_t)(r0 + 8) * ldc + col] = acc[mf][nf][2] + bx;
                }
            }
        }
    }
}

__global__ __launch_bounds__(256, 1)
void mma_gemm_kernel(const __nv_bfloat16* __restrict__ Ah,
                     const __nv_bfloat16* __restrict__ Al,
                     const __nv_bfloat16* __restrict__ Bh,
                     const __nv_bfloat16* __restrict__ Bl,
                     const float* __restrict__ bias,
                     float* __restrict__ C, int M, int N, int K) {
    extern __shared__ __align__(1024) char smem[];
    gemm_core(Ah, Al, Bh, Bl, bias, C, M, N, K, K, K, N,
              blockIdx.y * GBM, blockIdx.x * GBN, smem_u32(smem));
}

// ---------------------------------------------------------------------------
// Fused flash attention (round-12 variant: no softmax chain; proven).
// grid (9 row-blocks, 200 bh), block 256 (8 warps).
// ---------------------------------------------------------------------------
__global__ __launch_bounds__(256, 1)
void flash_kernel() {
    extern __shared__ __align__(1024) char smem[];
    const uint32_t sm0 = smem_u32(smem);
    const int tid = threadIdx.x;
    const int lane = tid & 31;
    const int warp = tid >> 5;
    const int bh = blockIdx.y;
    const int b = bh / kH, h = bh % kH;
    const int rowBase = blockIdx.x * 128;
    constexpr int NIT = kKP / 64;   // 17

    const __nv_bfloat16* qsrc[2] = {g_qh, g_ql};
    const __nv_bfloat16* ksrc[2] = {g_kh, g_kl};
    const __nv_bfloat16* vsrc[2] = {g_vth, g_vtl};

    // ---- q tile loads (lumped into group 0 with kv stage 0)
#pragma unroll
    for (int t = 0; t < 16; t++) {
        int cid = tid + (t << 8);           // 0..4095
        int split = cid >> 11;
        int p = (cid >> 10) & 1;
        int r = (cid >> 3) & 127;
        int ck = cid & 7;
        int lr = rowBase + r;
        int sz = (lr < kN) ? 16 : 0;
        int gr = (lr < kN) ? lr : 0;
        const void* gp = qsrc[split] + ((size_t)(b * kN + gr)) * kC + h * kD + p * 64 + ck * 8;
        uint32_t d = sm0 + (uint32_t)(split * 32768 + p * 16384)
                   + swz((uint32_t)((r << 7) + (ck << 4)));
        asm volatile("cp.async.cg.shared.global [%0], [%1], 16, %2;"
                     :: "r"(d), "l"(gp), "r"(sz));
    }

    auto load_kv = [&](int kt) {
        const uint32_t sb = sm0 + 65536u + (uint32_t)(kt & 1) * 65536u;
#pragma unroll
        for (int t = 0; t < 16; t++) {
            int cid = tid + (t << 8);       // 0..4095
            if (cid < 2048) {               // k: [split][panel][64 rows][128B]
                int split = cid >> 10;
                int p = (cid >> 9) & 1;
                int r = (cid >> 3) & 63;
                int ck = cid & 7;
                int gk = kt * 64 + r;
                int sz = (gk < kN) ? 16 : 0;
                int gr = (gk < kN) ? gk : 0;
                const void* gp = ksrc[split] + ((size_t)(b * kN + gr)) * kC + h * kD + p * 64 + ck * 8;
                uint32_t d = sb + (uint32_t)(split * 16384 + p * 8192)
                           + swz((uint32_t)((r << 7) + (ck << 4)));
                asm volatile("cp.async.cg.shared.global [%0], [%1], 16, %2;"
                             :: "r"(d), "l"(gp), "r"(sz));
            } else {                        // v^T: [split][128 d-rows][128B]
                int cid2 = cid - 2048;
                int split = cid2 >> 10;
                int r = (cid2 >> 3) & 127;
                int ck = cid2 & 7;
                const void* gp = vsrc[split] + ((size_t)(bh * kD + r)) * kKP + kt * 64 + ck * 8;
                uint32_t d = sb + 32768u + (uint32_t)(split * 16384)
                           + swz((uint32_t)((r << 7) + (ck << 4)));
                asm volatile("cp.async.cg.shared.global [%0], [%1], 16, 16;"
                             :: "r"(d), "l"(gp));
            }
        }
        asm volatile("cp.async.commit_group;" ::: "memory");
    };

    load_kv(0);   // commits group0 = q + kv0

    uint32_t aqh[8][4], aql[8][4];
    float accO[16][4];
#pragma unroll
    for (int nd = 0; nd < 16; nd++)
        accO[nd][0] = accO[nd][1] = accO[nd][2] = accO[nd][3] = 0.f;
    float l0r = 0.f, l1r = 0.f;   // per-lane partial row sums

    const uint32_t bRow = (uint32_t)(lane & 7);
    const uint32_t bHalf = (uint32_t)(((lane >> 3) & 1) << 4);

    for (int kt = 0; kt < NIT; kt++) {
        if (kt + 1 < NIT) {
            load_kv(kt + 1);
            asm volatile("cp.async.wait_group 1;" ::: "memory");
        } else {
            asm volatile("cp.async.wait_group 0;" ::: "memory");
        }
        __syncthreads();

        if (kt == 0) {  // preload q fragments (held in registers all iters)
            const uint32_t aRow = (uint32_t)(warp * 16 + (lane & 15));
            const uint32_t aHalf = (uint32_t)((lane >> 4) << 4);
#pragma unroll
            for (int ks = 0; ks < 8; ks++) {
                uint32_t p = (uint32_t)(ks >> 2);
                uint32_t kb = (uint32_t)((ks & 3) << 5);
                uint32_t off = swz((aRow << 7) + kb + aHalf);
                ldsm_x4(aqh[ks], sm0 + p * 16384 + off);
                ldsm_x4(aql[ks], sm0 + 32768 + p * 16384 + off);
            }
        }

        const uint32_t sb = sm0 + 65536u + (uint32_t)(kt & 1) * 65536u;

        // ---- S = q k^T : 16 rows x 64 keys per warp
        float accS[8][4];
#pragma unroll
        for (int nf = 0; nf < 8; nf++)
            accS[nf][0] = accS[nf][1] = accS[nf][2] = accS[nf][3] = 0.f;
#pragma unroll
        for (int ks = 0; ks < 8; ks++) {
            uint32_t p = (uint32_t)(ks >> 2);
            uint32_t kb = (uint32_t)((ks & 3) << 5);
#pragma unroll
            for (int nf = 0; nf < 8; nf++) {
                uint32_t off = swz((((uint32_t)(nf * 8) + bRow) << 7) + kb + bHalf);
                uint32_t bkh[2], bkl[2];
                ldsm_x2(bkh, sb + p * 8192 + off);
                ldsm_x2(bkl, sb + 16384 + p * 8192 + off);
                mma_bf16(accS[nf], aqh[ks], bkh);
                mma_bf16(accS[nf], aqh[ks], bkl);
                mma_bf16(accS[nf], aql[ks], bkh);
            }
        }

        // ---- mask invalid keys on last tile
        if (kt == NIT - 1) {
#pragma unroll
            for (int nf = 0; nf < 8; nf++) {
                int c0 = (NIT - 1) * 64 + nf * 8 + ((lane & 3) << 1);
                if (c0 >= kN)     { accS[nf][0] = -1e30f; accS[nf][2] = -1e30f; }
                if (c0 + 1 >= kN) { accS[nf][1] = -1e30f; accS[nf][3] = -1e30f; }
            }
        }

        // ---- exp (no max subtraction: logits O(1)) + per-lane l accumulation
#pragma unroll
        for (int nf = 0; nf < 8; nf++) {
            accS[nf][0] = __expf(accS[nf][0]);
            accS[nf][1] = __expf(accS[nf][1]);
            accS[nf][2] = __expf(accS[nf][2]);
            accS[nf][3] = __expf(accS[nf][3]);
            l0r += accS[nf][0] + accS[nf][1];
            l1r += accS[nf][2] + accS[nf][3];
        }

        // ---- O += P * V : P re-packed from C-fragments into A-fragments
#pragma unroll
        for (int j = 0; j < 4; j++) {   // key chunks of 16
            uint32_t aPh[4], aPl[4];
            const float* pA = accS[2 * j];
            const float* pB = accS[2 * j + 1];
            aPh[0] = packbf(pA[0], pA[1]);
            aPh[1] = packbf(pA[2], pA[3]);
            aPh[2] = packbf(pB[0], pB[1]);
            aPh[3] = packbf(pB[2], pB[3]);
            aPl[0] = packbf(bfres(pA[0]), bfres(pA[1]));
            aPl[1] = packbf(bfres(pA[2]), bfres(pA[3]));
            aPl[2] = packbf(bfres(pB[0]), bfres(pB[1]));
            aPl[3] = packbf(bfres(pB[2]), bfres(pB[3]));
#pragma unroll
            for (int nd = 0; nd < 16; nd++) {
                uint32_t off = swz((((uint32_t)(nd * 8) + bRow) << 7)
                                   + (uint32_t)(j * 32) + bHalf);
                uint32_t bvh[2], bvl[2];
                ldsm_x2(bvh, sb + 32768 + off);
                ldsm_x2(bvl, sb + 49152 + off);
                mma_bf16(accO[nd], aPh, bvh);
                mma_bf16(accO[nd], aPh, bvl);
                mma_bf16(accO[nd], aPl, bvh);
            }
        }
        __syncthreads();
    }

    // ---- epilogue: reduce l across the quad, divide, write bf16 splits
    l0r += __shfl_xor_sync(0xffffffffu, l0r, 1);
    l0r += __shfl_xor_sync(0xffffffffu, l0r, 2);
    l1r += __shfl_xor_sync(0xffffffffu, l1r, 1);
    l1r += __shfl_xor_sync(0xffffffffu, l1r, 2);
    float inv0 = 1.f / l0r, inv1 = 1.f / l1r;
    int r0g = rowBase + warp * 16 + (lane >> 2);
    int r1g = r0g + 8;
#pragma unroll
    for (int nd = 0; nd < 16; nd++) {
        int d0 = nd * 8 + ((lane & 3) << 1);
        if (r0g < kN) {
            float o0 = accO[nd][0] * inv0, o1 = accO[nd][1] * inv0;
            size_t off = ((size_t)(b * kN + r0g)) * kC + h * kD + d0;
            __nv_bfloat162 hv; hv.x = __float2bfloat16(o0); hv.y = __float2bfloat16(o1);
            *reinterpret_cast<__nv_bfloat162*>(g_aoh + off) = hv;
            __nv_bfloat162 lv;
            lv.x = __float2bfloat16(o0 - __bfloat162float(hv.x));
            lv.y = __float2bfloat16(o1 - __bfloat162float(hv.y));
            *reinterpret_cast<__nv_bfloat162*>(g_aol + off) = lv;
        }
        if (r1g < kN) {
            float o0 = accO[nd][2] * inv1, o1 = accO[nd][3] * inv1;
            size_t off = ((size_t)(b * kN + r1g)) * kC + h * kD + d0;
            __nv_bfloat162 hv; hv.x = __float2bfloat16(o0); hv.y = __float2bfloat16(o1);
            *reinterpret_cast<__nv_bfloat162*>(g_aoh + off) = hv;
            __nv_bfloat162 lv;
            lv.x = __float2bfloat16(o0 - __bfloat162float(hv.x));
            lv.y = __float2bfloat16(o1 - __bfloat162float(hv.y));
            *reinterpret_cast<__nv_bfloat162*>(g_aol + off) = lv;
        }
    }
}

// ---------------------------------------------------------------------------
// fp32 -> bf16 hi/lo split (elementwise)
// ---------------------------------------------------------------------------
__global__ void split_kernel(const float* __restrict__ src,
                             __nv_bfloat16* __restrict__ h,
                             __nv_bfloat16* __restrict__ l, int n4) {
    int i = blockIdx.x * blockDim.x + threadIdx.x;
    if (i >= n4) return;
    float4 v = ((const float4*)src)[i];
    __nv_bfloat162 h01, h23, l01, l23;
    __nv_bfloat16 hb;
    hb = __float2bfloat16(v.x); h01.x = hb; l01.x = __float2bfloat16(v.x - __bfloat162float(hb));
    hb = __float2bfloat16(v.y); h01.y = hb; l01.y = __float2bfloat16(v.y - __bfloat162float(hb));
    hb = __float2bfloat16(v.z); h23.x = hb; l23.x = __float2bfloat16(v.z - __bfloat162float(hb));
    hb = __float2bfloat16(v.w); h23.y = hb; l23.y = __float2bfloat16(v.w - __bfloat162float(hb));
    ((__nv_bfloat162*)h)[i * 2] = h01; ((__nv_bfloat162*)h)[i * 2 + 1] = h23;
    ((__nv_bfloat162*)l)[i * 2] = l01; ((__nv_bfloat162*)l)[i * 2 + 1] = l23;
}

// transpose + split: src[K,N] fp32 -> th/tl [N,K] bf16
__global__ void tsplit_kernel(const float* __restrict__ src,
                              __nv_bfloat16* __restrict__ th,
                              __nv_bfloat16* __restrict__ tl, int K, int N) {
    __shared__ float t[32][33];
    int n0 = blockIdx.x * 32, k0 = blockIdx.y * 32;
    int tx = threadIdx.x, ty = threadIdx.y;  // 32 x 8
#pragma unroll
    for (int i = 0; i < 32; i += 8)
        t[ty + i][tx] = src[(size_t)(k0 + ty + i) * N + n0 + tx];
    __syncthreads();
#pragma unroll
    for (int i = 0; i < 32; i += 8) {
        float v = t[tx][ty + i];
        __nv_bfloat16 hb = __float2bfloat16(v);
        size_t o = (size_t)(n0 + ty + i) * K + k0 + tx;
        th[o] = hb;
        tl[o] = __float2bfloat16(v - __bfloat162float(hb));
    }
}

// per-(b,h) V transpose+split: V[1025,128] -> Vt[128, kKP] zero-padded
__global__ void vtsplit_kernel() {
    __shared__ float t[32][33];
    const int bh = blockIdx.z;
    const int b = bh / kH, h = bh % kH;
    const float* V = g_qkv + (size_t)b * kN * kQKVN + 2 * kC + h * kD;
    const int k0 = blockIdx.x * 32, n0 = blockIdx.y * 32;
    const int tx = threadIdx.x, ty = threadIdx.y;
#pragma unroll
    for (int i = 0; i < 32; i += 8) {
        int kk = k0 + ty + i;
        t[ty + i][tx] = (kk < kN) ? V[(size_t)kk * kQKVN + n0 + tx] : 0.f;
    }
    __syncthreads();
    __nv_bfloat16* th = g_vth + (size_t)bh * kD * kKP;
    __nv_bfloat16* tl = g_vtl + (size_t)bh * kD * kKP;
#pragma unroll
    for (int i = 0; i < 32; i += 8) {
        float v = t[tx][ty + i];
        __nv_bfloat16 hb = __float2bfloat16(v);
        size_t o = (size_t)(n0 + ty + i) * kKP + k0 + tx;
        th[o] = hb;
        tl[o] = __float2bfloat16(v - __bfloat162float(hb));
    }
}

// ---------------------------------------------------------------------------
// RMSNorm over C on q,k -> bf16 hi/lo splits; q gets attn scale folded in.
// ---------------------------------------------------------------------------
__global__ void rmsnorm_kernel(const float* __restrict__ w_q,
                               const float* __restrict__ w_k) {
    const int m = blockIdx.x;
    const int which = blockIdx.y;
    const float* row = g_qkv + (size_t)m * kQKVN + which * kC;
    const float* w = which ? w_k : w_q;
    __nv_bfloat16* dh = (which ? g_kh : g_qh) + (size_t)m * kC;
    __nv_bfloat16* dl = (which ? g_kl : g_ql) + (size_t)m * kC;

    float ss = 0.f;
    for (int c = threadIdx.x; c < kC; c += 256) {
        float v = row[c];
        ss += v * v;
    }
#pragma unroll
    for (int o = 16; o > 0; o >>= 1) ss += __shfl_xor_sync(0xffffffffu, ss, o);
    __shared__ float sred[8];
    __shared__ float stot;
    int wid = threadIdx.x >> 5, lane = threadIdx.x & 31;
    if (lane == 0) sred[wid] = ss;
    __syncthreads();
    if (wid == 0) {
        float t = (lane < 8) ? sred[lane] : 0.f;
#pragma unroll
        for (int o = 4; o > 0; o >>= 1) t += __shfl_xor_sync(0xffffffffu, t, o);
        if (lane == 0) stot = t;
    }
    __syncthreads();
    float inv = rsqrtf(stot / (float)kC + kEps) * (which == 0 ? kScale : 1.f);
    for (int c = threadIdx.x; c < kC; c += 256) {
        float v = row[c] * inv * w[c];
        __nv_bfloat16 hb = __float2bfloat16(v);
        dh[c] = hb;
        dl[c] = __float2bfloat16(v - __bfloat162float(hb));
    }
}

// ---------------------------------------------------------------------------
extern "C" void kernel_launch(void* const* d_in, const int* in_sizes, int n_in,
                              void* d_out, int out_size) {
    const float* x      = (const float*)d_in[0];
    const float* qkv_w  = (const float*)d_in[1];
    const float* qkv_b  = (const float*)d_in[2];
    const float* q_norm = (const float*)d_in[3];
    const float* k_norm = (const float*)d_in[4];
    const float* proj_w = (const float*)d_in[5];
    const float* proj_b = (const float*)d_in[6];
    float* out = (float*)d_out;

    float* qkv_s;
    __nv_bfloat16 *xh, *xl, *w1h, *w1l, *w2h, *w2l, *aoh, *aol;
    cudaGetSymbolAddress((void**)&qkv_s, g_qkv);
    cudaGetSymbolAddress((void**)&xh, g_xh);
    cudaGetSymbolAddress((void**)&xl, g_xl);
    cudaGetSymbolAddress((void**)&w1h, g_w1h);
    cudaGetSymbolAddress((void**)&w1l, g_w1l);
    cudaGetSymbolAddress((void**)&w2h, g_w2h);
    cudaGetSymbolAddress((void**)&w2l, g_w2l);
    cudaGetSymbolAddress((void**)&aoh, g_aoh);
    cudaGetSymbolAddress((void**)&aol, g_aol);

    cudaFuncSetAttribute(mma_gemm_kernel,
                         cudaFuncAttributeMaxDynamicSharedMemorySize, TC_SMEM);
    cudaFuncSetAttribute(flash_kernel,
                         cudaFuncAttributeMaxDynamicSharedMemorySize, FL_SMEM);

    const int n4 = kM * kC / 4;
    // prep: splits + weight transposes
    split_kernel<<<(n4 + 255) / 256, 256>>>(x, xh, xl, n4);
    tsplit_kernel<<<dim3(kQKVN / 32, kC / 32), dim3(32, 8)>>>(qkv_w, w1h, w1l, kC, kQKVN);
    tsplit_kernel<<<dim3(kC / 32, kC / 32), dim3(32, 8)>>>(proj_w, w2h, w2l, kC, kC);

    // 1) qkv GEMM (HMMA, 3-stage)
    mma_gemm_kernel<<<dim3(kQKVN / GBN, (kM + GBM - 1) / GBM), 256, TC_SMEM>>>(
        xh, xl, w1h, w1l, qkv_b, qkv_s, kM, kQKVN, kC);
    // 2) rmsnorm q/k -> bf16 splits ; V transpose-split
    rmsnorm_kernel<<<dim3(kM, 2), 256>>>(q_norm, k_norm);
    vtsplit_kernel<<<dim3(kKP / 32, kD / 32, kB * kH), dim3(32, 8)>>>();
    // 3) fused flash attention -> O bf16 splits
    flash_kernel<<<dim3(9, kB * kH), 256, FL_SMEM>>>();
    // 4) proj GEMM (HMMA, 3-stage)
    mma_gemm_kernel<<<dim3(kC / GBN, (kM + GBM - 1) / GBM), 256, TC_SMEM>>>(
        aoh, aol, w2h, w2l, proj_b, out, kM, kC, kC);
}

// round 15
// speedup vs baseline: 1.1153x; 1.1153x over previous
#include <cuda_runtime.h>
#include <cuda_bf16.h>
#include <cstdint>
#include <cstddef>

// ---------------------------------------------------------------------------
// InternVL2.5 Attention: B=8, N=1025, C=3200, H=25, D=128
// Round 14: dense GEMM re-tiled 128x64 with __launch_bounds__(256,2) ->
// 2 CTAs/SM (4 warps/SMSP) to hide LDSM->MMA latency. 2-stage pipeline
// (R12-proven). Flash middle unchanged (R12).
// ---------------------------------------------------------------------------

namespace {
constexpr int kB = 8, kN = 1025, kC = 3200, kH = 25, kD = 128;
constexpr int kM = kB * kN;          // 8200
constexpr int kQKVN = 3 * kC;        // 9600
constexpr int kKP = 1088;            // padded key count (17*64)
constexpr float kScale = 0.08838834764831845f;
constexpr float kEps = 1e-6f;

// mma.sync dense GEMM config: 128x64 CTA tile, 2 CTAs/SM
constexpr int GBM = 128, GBN = 64, GBK = 64;
constexpr int TILE_A = GBM * GBK * 2;          // 16 KB (per A split tensor)
constexpr int TILE_Bt = GBN * GBK * 2;         // 8 KB (per B split tensor)
constexpr int STAGE_B = 2 * TILE_A + 2 * TILE_Bt;  // 48 KB
constexpr int TC_SMEM = 2 * STAGE_B;           // 96 KB per CTA

// flash kernel smem: q 64KB + 2 stages x 64KB (k 32KB + v 32KB)
constexpr int FL_SMEM = 3 * 65536;             // 192 KB
}  // namespace

// ---------------- scratch (__device__ globals; no allocation allowed) -------
__device__ float g_qkv[(size_t)8200 * 9600];                // 315 MB
__device__ __nv_bfloat16 g_xh[26240000], g_xl[26240000];
__device__ __nv_bfloat16 g_w1h[30720000], g_w1l[30720000];  // qkv_w^T
__device__ __nv_bfloat16 g_w2h[10240000], g_w2l[10240000];  // proj_w^T
__device__ __nv_bfloat16 g_aoh[26240000], g_aol[26240000];  // O splits
__device__ __nv_bfloat16 g_qh[26240000], g_ql[26240000];    // q split
__device__ __nv_bfloat16 g_kh[26240000], g_kl[26240000];    // k split
__device__ __nv_bfloat16 g_vth[(size_t)200 * 128 * kKP];    // V^T split
__device__ __nv_bfloat16 g_vtl[(size_t)200 * 128 * kKP];

// ---------------- PTX helpers ----------------------------------------------
__device__ __forceinline__ uint32_t smem_u32(const void* p) {
    uint32_t a;
    asm("{ .reg .u64 t; cvta.to.shared.u64 t, %1; cvt.u32.u64 %0, t; }"
        : "=r"(a) : "l"(p));
    return a;
}
__device__ __forceinline__ void ldsm_x4(uint32_t (&r)[4], uint32_t addr) {
    asm volatile("ldmatrix.sync.aligned.m8n8.x4.shared.b16 {%0,%1,%2,%3}, [%4];"
                 : "=r"(r[0]), "=r"(r[1]), "=r"(r[2]), "=r"(r[3]) : "r"(addr));
}
__device__ __forceinline__ void ldsm_x2(uint32_t (&r)[2], uint32_t addr) {
    asm volatile("ldmatrix.sync.aligned.m8n8.x2.shared.b16 {%0,%1}, [%2];"
                 : "=r"(r[0]), "=r"(r[1]) : "r"(addr));
}
__device__ __forceinline__ void mma_bf16(float (&d)[4], const uint32_t (&a)[4],
                                         const uint32_t (&b)[2]) {
    asm volatile(
        "mma.sync.aligned.m16n8k16.row.col.f32.bf16.bf16.f32 "
        "{%0,%1,%2,%3}, {%4,%5,%6,%7}, {%8,%9}, {%0,%1,%2,%3};"
        : "+f"(d[0]), "+f"(d[1]), "+f"(d[2]), "+f"(d[3])
        : "r"(a[0]), "r"(a[1]), "r"(a[2]), "r"(a[3]), "r"(b[0]), "r"(b[1]));
}
__device__ __forceinline__ void mma_bf16s(float (&d)[4], const uint32_t (&a)[4],
                                          uint32_t b0, uint32_t b1) {
    asm volatile(
        "mma.sync.aligned.m16n8k16.row.col.f32.bf16.bf16.f32 "
        "{%0,%1,%2,%3}, {%4,%5,%6,%7}, {%8,%9}, {%0,%1,%2,%3};"
        : "+f"(d[0]), "+f"(d[1]), "+f"(d[2]), "+f"(d[3])
        : "r"(a[0]), "r"(a[1]), "r"(a[2]), "r"(a[3]), "r"(b0), "r"(b1));
}
__device__ __forceinline__ uint32_t swz(uint32_t off) {
    return off ^ ((off >> 3) & 0x70);
}
__device__ __forceinline__ uint32_t packbf(float lo, float hi) {
    __nv_bfloat162 h;
    h.x = __float2bfloat16(lo);
    h.y = __float2bfloat16(hi);
    return *reinterpret_cast<uint32_t*>(&h);
}
__device__ __forceinline__ float bfres(float v) {
    return v - __bfloat162float(__float2bfloat16(v));
}

// ---------------------------------------------------------------------------
// HMMA dense GEMM, 128x64 tile, 2-stage pipeline, 2 CTAs/SM:
// C[M,N] = Ahl[M,K]*(Bhl[N,K])^T + bias
// ---------------------------------------------------------------------------
__global__ __launch_bounds__(256, 2)
void mma_gemm_kernel(const __nv_bfloat16* __restrict__ Ah,
                     const __nv_bfloat16* __restrict__ Al,
                     const __nv_bfloat16* __restrict__ Bh,
                     const __nv_bfloat16* __restrict__ Bl,
                     const float* __restrict__ bias,
                     float* __restrict__ C, int M, int N, int K) {
    extern __shared__ __align__(1024) char smem[];
    const uint32_t sm0 = smem_u32(smem);
    const int tid = threadIdx.x;
    const int lane = tid & 31;
    const int warp = tid >> 5;
    const int m0 = (warp >> 1) * 32;   // warp tile: 32 rows x 32 cols
    const int n0 = (warp & 1) * 32;
    const int rowBase = blockIdx.y * GBM;
    const int colBase = blockIdx.x * GBN;
    const int nChunks = K / GBK;

    float acc[2][4][4] = {};

    auto load_stage = [&](int c) {
        const uint32_t sb = sm0 + (uint32_t)(c & 1) * STAGE_B;
        const int k0 = c * GBK;
#pragma unroll
        for (int t = 0; t < 12; t++) {
            int cid = tid + (t << 8);          // 0..3071
            const __nv_bfloat16* bp;
            int r, ck, g0, lim;
            uint32_t dst;
            if (cid < 2048) {                  // A: Ah/Al, 128 rows x 8 chunks
                int split = cid >> 10;
                r = (cid >> 3) & 127;
                ck = cid & 7;
                g0 = rowBase + r;
                lim = M;
                bp = split ? Al : Ah;
                dst = sb + (uint32_t)(split * TILE_A)
                    + swz((uint32_t)((r << 7) + (ck << 4)));
            } else {                           // B: Bh/Bl, 64 rows x 8 chunks
                int cid2 = cid - 2048;
                int split = cid2 >> 9;
                r = (cid2 >> 3) & 63;
                ck = cid2 & 7;
                g0 = colBase + r;
                lim = N;
                bp = split ? Bl : Bh;
                dst = sb + (uint32_t)(2 * TILE_A + split * TILE_Bt)
                    + swz((uint32_t)((r << 7) + (ck << 4)));
            }
            int sz = (g0 < lim) ? 16 : 0;
            int ga = (g0 < lim) ? g0 : 0;
            const void* gp = bp + (size_t)ga * K + k0 + (ck << 3);
            asm volatile("cp.async.cg.shared.global [%0], [%1], 16, %2;"
                         :: "r"(dst), "l"(gp), "r"(sz));
        }
        asm volatile("cp.async.commit_group;" ::: "memory");
    };

    auto compute_stage = [&](int s) {
        const uint32_t sb = sm0 + (uint32_t)s * STAGE_B;
        const uint32_t aRowA = (uint32_t)(m0 + (lane & 15));
        const uint32_t aByteHalf = (uint32_t)((lane >> 4) << 4);
        const uint32_t bRow = (uint32_t)(n0 + (lane & 7) + ((lane >> 4) << 3));
        const uint32_t bByteHalf = (uint32_t)(((lane >> 3) & 1) << 4);
#pragma unroll
        for (int ks = 0; ks < 4; ks++) {
            const uint32_t kb = (uint32_t)(ks << 5);
            uint32_t bh4[2][4], bl4[2][4];
#pragma unroll
            for (int nfp = 0; nfp < 2; nfp++) {
                uint32_t off = (((bRow + (uint32_t)(nfp * 16)) << 7) + kb + bByteHalf);
                uint32_t sa = swz(off);
                ldsm_x4(bh4[nfp], sb + 2 * TILE_A + sa);
                ldsm_x4(bl4[nfp], sb + 2 * TILE_A + TILE_Bt + sa);
            }
#pragma unroll
            for (int mf = 0; mf < 2; mf++) {
                uint32_t off = (((aRowA + mf * 16) << 7) + kb + aByteHalf);
                uint32_t sa = swz(off);
                uint32_t a[4];
                ldsm_x4(a, sb + sa);                 // Ah
#pragma unroll
                for (int nf = 0; nf < 4; nf++) {
                    mma_bf16s(acc[mf][nf], a, bh4[nf >> 1][(nf & 1) * 2],
                              bh4[nf >> 1][(nf & 1) * 2 + 1]);
                    mma_bf16s(acc[mf][nf], a, bl4[nf >> 1][(nf & 1) * 2],
                              bl4[nf >> 1][(nf & 1) * 2 + 1]);
                }
                ldsm_x4(a, sb + TILE_A + sa);        // Al
#pragma unroll
                for (int nf = 0; nf < 4; nf++)
                    mma_bf16s(acc[mf][nf], a, bh4[nf >> 1][(nf & 1) * 2],
                              bh4[nf >> 1][(nf & 1) * 2 + 1]);
            }
        }
    };

    // 2-stage pipeline (R12-proven structure)
    load_stage(0);
    for (int c = 0; c < nChunks; c++) {
        if (c + 1 < nChunks) {
            load_stage(c + 1);
            asm volatile("cp.async.wait_group 1;" ::: "memory");
        } else {
            asm volatile("cp.async.wait_group 0;" ::: "memory");
        }
        __syncthreads();
        compute_stage(c & 1);
        __syncthreads();
    }

#pragma unroll
    for (int mf = 0; mf < 2; mf++) {
        int r0 = rowBase + m0 + mf * 16 + (lane >> 2);
#pragma unroll
        for (int nf = 0; nf < 4; nf++) {
            int col = colBase + n0 + nf * 8 + ((lane & 3) << 1);
            float bx = 0.f, by = 0.f;
            if (bias && col + 1 < N) { float2 bv = *(const float2*)&bias[col]; bx = bv.x; by = bv.y; }
            if (r0 < M) {
                if (col + 1 < N) {
                    float2 o = {acc[mf][nf][0] + bx, acc[mf][nf][1] + by};
                    *(float2*)&C[(size_t)r0 * N + col] = o;
                } else if (col < N) {
                    C[(size_t)r0 * N + col] = acc[mf][nf][0] + bx;
                }
            }
            if (r0 + 8 < M) {
                if (col + 1 < N) {
                    float2 o = {acc[mf][nf][2] + bx, acc[mf][nf][3] + by};
                    *(float2*)&C[(size_t)(r0 + 8) * N + col] = o;
                } else if (col < N) {
                    C[(size_t)(r0 + 8) * N + col] = acc[mf][nf][2] + bx;
                }
            }
        }
    }
}

// ---------------------------------------------------------------------------
// Fused flash attention (round-12 variant, byte-identical).
// grid (9 row-blocks, 200 bh), block 256 (8 warps).
// ---------------------------------------------------------------------------
__global__ __launch_bounds__(256, 1)
void flash_kernel() {
    extern __shared__ __align__(1024) char smem[];
    const uint32_t sm0 = smem_u32(smem);
    const int tid = threadIdx.x;
    const int lane = tid & 31;
    const int warp = tid >> 5;
    const int bh = blockIdx.y;
    const int b = bh / kH, h = bh % kH;
    const int rowBase = blockIdx.x * 128;
    constexpr int NIT = kKP / 64;   // 17

    const __nv_bfloat16* qsrc[2] = {g_qh, g_ql};
    const __nv_bfloat16* ksrc[2] = {g_kh, g_kl};
    const __nv_bfloat16* vsrc[2] = {g_vth, g_vtl};

    // ---- q tile loads (lumped into group 0 with kv stage 0)
#pragma unroll
    for (int t = 0; t < 16; t++) {
        int cid = tid + (t << 8);           // 0..4095
        int split = cid >> 11;
        int p = (cid >> 10) & 1;
        int r = (cid >> 3) & 127;
        int ck = cid & 7;
        int lr = rowBase + r;
        int sz = (lr < kN) ? 16 : 0;
        int gr = (lr < kN) ? lr : 0;
        const void* gp = qsrc[split] + ((size_t)(b * kN + gr)) * kC + h * kD + p * 64 + ck * 8;
        uint32_t d = sm0 + (uint32_t)(split * 32768 + p * 16384)
                   + swz((uint32_t)((r << 7) + (ck << 4)));
        asm volatile("cp.async.cg.shared.global [%0], [%1], 16, %2;"
                     :: "r"(d), "l"(gp), "r"(sz));
    }

    auto load_kv = [&](int kt) {
        const uint32_t sb = sm0 + 65536u + (uint32_t)(kt & 1) * 65536u;
#pragma unroll
        for (int t = 0; t < 16; t++) {
            int cid = tid + (t << 8);       // 0..4095
            if (cid < 2048) {               // k: [split][panel][64 rows][128B]
                int split = cid >> 10;
                int p = (cid >> 9) & 1;
                int r = (cid >> 3) & 63;
                int ck = cid & 7;
                int gk = kt * 64 + r;
                int sz = (gk < kN) ? 16 : 0;
                int gr = (gk < kN) ? gk : 0;
                const void* gp = ksrc[split] + ((size_t)(b * kN + gr)) * kC + h * kD + p * 64 + ck * 8;
                uint32_t d = sb + (uint32_t)(split * 16384 + p * 8192)
                           + swz((uint32_t)((r << 7) + (ck << 4)));
                asm volatile("cp.async.cg.shared.global [%0], [%1], 16, %2;"
                             :: "r"(d), "l"(gp), "r"(sz));
            } else {                        // v^T: [split][128 d-rows][128B]
                int cid2 = cid - 2048;
                int split = cid2 >> 10;
                int r = (cid2 >> 3) & 127;
                int ck = cid2 & 7;
                const void* gp = vsrc[split] + ((size_t)(bh * kD + r)) * kKP + kt * 64 + ck * 8;
                uint32_t d = sb + 32768u + (uint32_t)(split * 16384)
                           + swz((uint32_t)((r << 7) + (ck << 4)));
                asm volatile("cp.async.cg.shared.global [%0], [%1], 16, 16;"
                             :: "r"(d), "l"(gp));
            }
        }
        asm volatile("cp.async.commit_group;" ::: "memory");
    };

    load_kv(0);   // commits group0 = q + kv0

    uint32_t aqh[8][4], aql[8][4];
    float accO[16][4];
#pragma unroll
    for (int nd = 0; nd < 16; nd++)
        accO[nd][0] = accO[nd][1] = accO[nd][2] = accO[nd][3] = 0.f;
    float l0r = 0.f, l1r = 0.f;   // per-lane partial row sums

    const uint32_t bRow = (uint32_t)(lane & 7);
    const uint32_t bHalf = (uint32_t)(((lane >> 3) & 1) << 4);

    for (int kt = 0; kt < NIT; kt++) {
        if (kt + 1 < NIT) {
            load_kv(kt + 1);
            asm volatile("cp.async.wait_group 1;" ::: "memory");
        } else {
            asm volatile("cp.async.wait_group 0;" ::: "memory");
        }
        __syncthreads();

        if (kt == 0) {  // preload q fragments (held in registers all iters)
            const uint32_t aRow = (uint32_t)(warp * 16 + (lane & 15));
            const uint32_t aHalf = (uint32_t)((lane >> 4) << 4);
#pragma unroll
            for (int ks = 0; ks < 8; ks++) {
                uint32_t p = (uint32_t)(ks >> 2);
                uint32_t kb = (uint32_t)((ks & 3) << 5);
                uint32_t off = swz((aRow << 7) + kb + aHalf);
                ldsm_x4(aqh[ks], sm0 + p * 16384 + off);
                ldsm_x4(aql[ks], sm0 + 32768 + p * 16384 + off);
            }
        }

        const uint32_t sb = sm0 + 65536u + (uint32_t)(kt & 1) * 65536u;

        // ---- S = q k^T : 16 rows x 64 keys per warp
        float accS[8][4];
#pragma unroll
        for (int nf = 0; nf < 8; nf++)
            accS[nf][0] = accS[nf][1] = accS[nf][2] = accS[nf][3] = 0.f;
#pragma unroll
        for (int ks = 0; ks < 8; ks++) {
            uint32_t p = (uint32_t)(ks >> 2);
            uint32_t kb = (uint32_t)((ks & 3) << 5);
#pragma unroll
            for (int nf = 0; nf < 8; nf++) {
                uint32_t off = swz((((uint32_t)(nf * 8) + bRow) << 7) + kb + bHalf);
                uint32_t bkh[2], bkl[2];
                ldsm_x2(bkh, sb + p * 8192 + off);
                ldsm_x2(bkl, sb + 16384 + p * 8192 + off);
                mma_bf16(accS[nf], aqh[ks], bkh);
                mma_bf16(accS[nf], aqh[ks], bkl);
                mma_bf16(accS[nf], aql[ks], bkh);
            }
        }

        // ---- mask invalid keys on last tile
        if (kt == NIT - 1) {
#pragma unroll
            for (int nf = 0; nf < 8; nf++) {
                int c0 = (NIT - 1) * 64 + nf * 8 + ((lane & 3) << 1);
                if (c0 >= kN)     { accS[nf][0] = -1e30f; accS[nf][2] = -1e30f; }
                if (c0 + 1 >= kN) { accS[nf][1] = -1e30f; accS[nf][3] = -1e30f; }
            }
        }

        // ---- exp (no max subtraction: logits O(1)) + per-lane l accumulation
#pragma unroll
        for (int nf = 0; nf < 8; nf++) {
            accS[nf][0] = __expf(accS[nf][0]);
            accS[nf][1] = __expf(accS[nf][1]);
            accS[nf][2] = __expf(accS[nf][2]);
            accS[nf][3] = __expf(accS[nf][3]);
            l0r += accS[nf][0] + accS[nf][1];
            l1r += accS[nf][2] + accS[nf][3];
        }

        // ---- O += P * V : P re-packed from C-fragments into A-fragments
#pragma unroll
        for (int j = 0; j < 4; j++) {   // key chunks of 16
            uint32_t aPh[4], aPl[4];
            const float* pA = accS[2 * j];
            const float* pB = accS[2 * j + 1];
            aPh[0] = packbf(pA[0], pA[1]);
            aPh[1] = packbf(pA[2], pA[3]);
            aPh[2] = packbf(pB[0], pB[1]);
            aPh[3] = packbf(pB[2], pB[3]);
            aPl[0] = packbf(bfres(pA[0]), bfres(pA[1]));
            aPl[1] = packbf(bfres(pA[2]), bfres(pA[3]));
            aPl[2] = packbf(bfres(pB[0]), bfres(pB[1]));
            aPl[3] = packbf(bfres(pB[2]), bfres(pB[3]));
#pragma unroll
            for (int nd = 0; nd < 16; nd++) {
                uint32_t off = swz((((uint32_t)(nd * 8) + bRow) << 7)
                                   + (uint32_t)(j * 32) + bHalf);
                uint32_t bvh[2], bvl[2];
                ldsm_x2(bvh, sb + 32768 + off);
                ldsm_x2(bvl, sb + 49152 + off);
                mma_bf16(accO[nd], aPh, bvh);
                mma_bf16(accO[nd], aPh, bvl);
                mma_bf16(accO[nd], aPl, bvh);
            }
        }
        __syncthreads();
    }

    // ---- epilogue: reduce l across the quad, divide, write bf16 splits
    l0r += __shfl_xor_sync(0xffffffffu, l0r, 1);
    l0r += __shfl_xor_sync(0xffffffffu, l0r, 2);
    l1r += __shfl_xor_sync(0xffffffffu, l1r, 1);
    l1r += __shfl_xor_sync(0xffffffffu, l1r, 2);
    float inv0 = 1.f / l0r, inv1 = 1.f / l1r;
    int r0g = rowBase + warp * 16 + (lane >> 2);
    int r1g = r0g + 8;
#pragma unroll
    for (int nd = 0; nd < 16; nd++) {
        int d0 = nd * 8 + ((lane & 3) << 1);
        if (r0g < kN) {
            float o0 = accO[nd][0] * inv0, o1 = accO[nd][1] * inv0;
            size_t off = ((size_t)(b * kN + r0g)) * kC + h * kD + d0;
            __nv_bfloat162 hv; hv.x = __float2bfloat16(o0); hv.y = __float2bfloat16(o1);
            *reinterpret_cast<__nv_bfloat162*>(g_aoh + off) = hv;
            __nv_bfloat162 lv;
            lv.x = __float2bfloat16(o0 - __bfloat162float(hv.x));
            lv.y = __float2bfloat16(o1 - __bfloat162float(hv.y));
            *reinterpret_cast<__nv_bfloat162*>(g_aol + off) = lv;
        }
        if (r1g < kN) {
            float o0 = accO[nd][2] * inv1, o1 = accO[nd][3] * inv1;
            size_t off = ((size_t)(b * kN + r1g)) * kC + h * kD + d0;
            __nv_bfloat162 hv; hv.x = __float2bfloat16(o0); hv.y = __float2bfloat16(o1);
            *reinterpret_cast<__nv_bfloat162*>(g_aoh + off) = hv;
            __nv_bfloat162 lv;
            lv.x = __float2bfloat16(o0 - __bfloat162float(hv.x));
            lv.y = __float2bfloat16(o1 - __bfloat162float(hv.y));
            *reinterpret_cast<__nv_bfloat162*>(g_aol + off) = lv;
        }
    }
}

// ---------------------------------------------------------------------------
// fp32 -> bf16 hi/lo split (elementwise)
// ---------------------------------------------------------------------------
__global__ void split_kernel(const float* __restrict__ src,
                             __nv_bfloat16* __restrict__ h,
                             __nv_bfloat16* __restrict__ l, int n4) {
    int i = blockIdx.x * blockDim.x + threadIdx.x;
    if (i >= n4) return;
    float4 v = ((const float4*)src)[i];
    __nv_bfloat162 h01, h23, l01, l23;
    __nv_bfloat16 hb;
    hb = __float2bfloat16(v.x); h01.x = hb; l01.x = __float2bfloat16(v.x - __bfloat162float(hb));
    hb = __float2bfloat16(v.y); h01.y = hb; l01.y = __float2bfloat16(v.y - __bfloat162float(hb));
    hb = __float2bfloat16(v.z); h23.x = hb; l23.x = __float2bfloat16(v.z - __bfloat162float(hb));
    hb = __float2bfloat16(v.w); h23.y = hb; l23.y = __float2bfloat16(v.w - __bfloat162float(hb));
    ((__nv_bfloat162*)h)[i * 2] = h01; ((__nv_bfloat162*)h)[i * 2 + 1] = h23;
    ((__nv_bfloat162*)l)[i * 2] = l01; ((__nv_bfloat162*)l)[i * 2 + 1] = l23;
}

// transpose + split: src[K,N] fp32 -> th/tl [N,K] bf16
__global__ void tsplit_kernel(const float* __restrict__ src,
                              __nv_bfloat16* __restrict__ th,
                              __nv_bfloat16* __restrict__ tl, int K, int N) {
    __shared__ float t[32][33];
    int n0 = blockIdx.x * 32, k0 = blockIdx.y * 32;
    int tx = threadIdx.x, ty = threadIdx.y;  // 32 x 8
#pragma unroll
    for (int i = 0; i < 32; i += 8)
        t[ty + i][tx] = src[(size_t)(k0 + ty + i) * N + n0 + tx];
    __syncthreads();
#pragma unroll
    for (int i = 0; i < 32; i += 8) {
        float v = t[tx][ty + i];
        __nv_bfloat16 hb = __float2bfloat16(v);
        size_t o = (size_t)(n0 + ty + i) * K + k0 + tx;
        th[o] = hb;
        tl[o] = __float2bfloat16(v - __bfloat162float(hb));
    }
}

// per-(b,h) V transpose+split: V[1025,128] -> Vt[128, kKP] zero-padded
__global__ void vtsplit_kernel() {
    __shared__ float t[32][33];
    const int bh = blockIdx.z;
    const int b = bh / kH, h = bh % kH;
    const float* V = g_qkv + (size_t)b * kN * kQKVN + 2 * kC + h * kD;
    const int k0 = blockIdx.x * 32, n0 = blockIdx.y * 32;
    const int tx = threadIdx.x, ty = threadIdx.y;
#pragma unroll
    for (int i = 0; i < 32; i += 8) {
        int kk = k0 + ty + i;
        t[ty + i][tx] = (kk < kN) ? V[(size_t)kk * kQKVN + n0 + tx] : 0.f;
    }
    __syncthreads();
    __nv_bfloat16* th = g_vth + (size_t)bh * kD * kKP;
    __nv_bfloat16* tl = g_vtl + (size_t)bh * kD * kKP;
#pragma unroll
    for (int i = 0; i < 32; i += 8) {
        float v = t[tx][ty + i];
        __nv_bfloat16 hb = __float2bfloat16(v);
        size_t o = (size_t)(n0 + ty + i) * kKP + k0 + tx;
        th[o] = hb;
        tl[o] = __float2bfloat16(v - __bfloat162float(hb));
    }
}

// ---------------------------------------------------------------------------
// RMSNorm over C on q,k -> bf16 hi/lo splits; q gets attn scale folded in.
// ---------------------------------------------------------------------------
__global__ void rmsnorm_kernel(const float* __restrict__ w_q,
                               const float* __restrict__ w_k) {
    const int m = blockIdx.x;
    const int which = blockIdx.y;
    const float* row = g_qkv + (size_t)m * kQKVN + which * kC;
    const float* w = which ? w_k : w_q;
    __nv_bfloat16* dh = (which ? g_kh : g_qh) + (size_t)m * kC;
    __nv_bfloat16* dl = (which ? g_kl : g_ql) + (size_t)m * kC;

    float ss = 0.f;
    for (int c = threadIdx.x; c < kC; c += 256) {
        float v = row[c];
        ss += v * v;
    }
#pragma unroll
    for (int o = 16; o > 0; o >>= 1) ss += __shfl_xor_sync(0xffffffffu, ss, o);
    __shared__ float sred[8];
    __shared__ float stot;
    int wid = threadIdx.x >> 5, lane = threadIdx.x & 31;
    if (lane == 0) sred[wid] = ss;
    __syncthreads();
    if (wid == 0) {
        float t = (lane < 8) ? sred[lane] : 0.f;
#pragma unroll
        for (int o = 4; o > 0; o >>= 1) t += __shfl_xor_sync(0xffffffffu, t, o);
        if (lane == 0) stot = t;
    }
    __syncthreads();
    float inv = rsqrtf(stot / (float)kC + kEps) * (which == 0 ? kScale : 1.f);
    for (int c = threadIdx.x; c < kC; c += 256) {
        float v = row[c] * inv * w[c];
        __nv_bfloat16 hb = __float2bfloat16(v);
        dh[c] = hb;
        dl[c] = __float2bfloat16(v - __bfloat162float(hb));
    }
}

// ---------------------------------------------------------------------------
extern "C" void kernel_launch(void* const* d_in, const int* in_sizes, int n_in,
                              void* d_out, int out_size) {
    const float* x      = (const float*)d_in[0];
    const float* qkv_w  = (const float*)d_in[1];
    const float* qkv_b  = (const float*)d_in[2];
    const float* q_norm = (const float*)d_in[3];
    const float* k_norm = (const float*)d_in[4];
    const float* proj_w = (const float*)d_in[5];
    const float* proj_b = (const float*)d_in[6];
    float* out = (float*)d_out;

    float* qkv_s;
    __nv_bfloat16 *xh, *xl, *w1h, *w1l, *w2h, *w2l, *aoh, *aol;
    cudaGetSymbolAddress((void**)&qkv_s, g_qkv);
    cudaGetSymbolAddress((void**)&xh, g_xh);
    cudaGetSymbolAddress((void**)&xl, g_xl);
    cudaGetSymbolAddress((void**)&w1h, g_w1h);
    cudaGetSymbolAddress((void**)&w1l, g_w1l);
    cudaGetSymbolAddress((void**)&w2h, g_w2h);
    cudaGetSymbolAddress((void**)&w2l, g_w2l);
    cudaGetSymbolAddress((void**)&aoh, g_aoh);
    cudaGetSymbolAddress((void**)&aol, g_aol);

    cudaFuncSetAttribute(mma_gemm_kernel,
                         cudaFuncAttributeMaxDynamicSharedMemorySize, TC_SMEM);
    cudaFuncSetAttribute(flash_kernel,
                         cudaFuncAttributeMaxDynamicSharedMemorySize, FL_SMEM);

    const int n4 = kM * kC / 4;
    // prep: splits + weight transposes
    split_kernel<<<(n4 + 255) / 256, 256>>>(x, xh, xl, n4);
    tsplit_kernel<<<dim3(kQKVN / 32, kC / 32), dim3(32, 8)>>>(qkv_w, w1h, w1l, kC, kQKVN);
    tsplit_kernel<<<dim3(kC / 32, kC / 32), dim3(32, 8)>>>(proj_w, w2h, w2l, kC, kC);

    // 1) qkv GEMM (HMMA, 128x64 tiles, 2 CTAs/SM)
    mma_gemm_kernel<<<dim3(kQKVN / GBN, (kM + GBM - 1) / GBM), 256, TC_SMEM>>>(
        xh, xl, w1h, w1l, qkv_b, qkv_s, kM, kQKVN, kC);
    // 2) rmsnorm q/k -> bf16 splits ; V transpose-split
    rmsnorm_kernel<<<dim3(kM, 2), 256>>>(q_norm, k_norm);
    vtsplit_kernel<<<dim3(kKP / 32, kD / 32, kB * kH), dim3(32, 8)>>>();
    // 3) fused flash attention -> O bf16 splits
    flash_kernel<<<dim3(9, kB * kH), 256, FL_SMEM>>>();
    // 4) proj GEMM (HMMA, 128x64 tiles, 2 CTAs/SM)
    mma_gemm_kernel<<<dim3(kC / GBN, (kM + GBM - 1) / GBM), 256, TC_SMEM>>>(
        aoh, aol, w2h, w2l, proj_b, out, kM, kC, kC);
}